// round 15
// baseline (speedup 1.0000x reference)
#include <cuda_runtime.h>
#include <math.h>

// ---------------- scratch (no allocs allowed) ----------------
#define MAX_T (64 * 4096)
#define MAX_B 64
__device__ float g_dot[MAX_T];       // per-node dot(logits, proj)
__device__ int   g_sub[MAX_T];       // per-graph subtract lists (stride N)
__device__ int   g_add[MAX_T];       // per-graph add lists (stride N)
__device__ int   g_subCnt[MAX_B];
__device__ int   g_addCnt[MAX_B];
__device__ float g_tlo;              // speculative accumulation threshold

// ---------------- kernel 1: dot + speculative accumulate ----------------
// One warp per 4 rows (512 thr = 64 rows/block; block never straddles a graph).
// After computing each row's dot, rows with dot > t_lo (~24%) are accumulated
// into register float4s (data already in registers -> no re-read), block-
// reduced in smem, and atomically added to out. t_lo = 0.72*||proj||, ~5.4
// sigma below the expected top-20% threshold of N(0,||p||^2) dots.
__global__ void __launch_bounds__(512)
dot_acc_kernel(const float* __restrict__ logits,
               const float* __restrict__ proj,
               float* __restrict__ dots,
               float* __restrict__ out,
               int blocksPerGraph, int D) {
    __shared__ float4 pS[64];
    __shared__ float4 sA[16][32];   // per-warp accumulators, cols 0..127
    __shared__ float4 sC[16][32];   // cols 128..255

    int tid = threadIdx.x;
    if (tid < 64) pS[tid] = reinterpret_cast<const float4*>(proj)[tid];
    __syncthreads();

    int warp = tid >> 5, lane = tid & 31;
    int row0 = (blockIdx.x * 16 + warp) * 4;

    float4 pa = pS[lane];
    float4 pc = pS[lane + 32];

    // ||proj||^2 via warp reduce (identical in every warp)
    float nrm = pa.x * pa.x + pa.y * pa.y + pa.z * pa.z + pa.w * pa.w
              + pc.x * pc.x + pc.y * pc.y + pc.z * pc.z + pc.w * pc.w;
#pragma unroll
    for (int o = 16; o; o >>= 1) nrm += __shfl_xor_sync(0xFFFFFFFFu, nrm, o);
    float tlo = 0.72f * sqrtf(nrm);
    if (blockIdx.x == 0 && tid == 0) g_tlo = tlo;

    const float4* rp = reinterpret_cast<const float4*>(logits) + (size_t)row0 * 64;

    float4 a[4], c[4];
#pragma unroll
    for (int r = 0; r < 4; r++) {
        a[r] = rp[(size_t)r * 64 + lane];
        c[r] = rp[(size_t)r * 64 + lane + 32];
    }

    float4 accA = make_float4(0.f, 0.f, 0.f, 0.f);
    float4 accC = make_float4(0.f, 0.f, 0.f, 0.f);
    float s[4];
#pragma unroll
    for (int r = 0; r < 4; r++) {
        s[r] = a[r].x * pa.x + a[r].y * pa.y + a[r].z * pa.z + a[r].w * pa.w
             + c[r].x * pc.x + c[r].y * pc.y + c[r].z * pc.z + c[r].w * pc.w;
#pragma unroll
        for (int o = 16; o; o >>= 1) s[r] += __shfl_xor_sync(0xFFFFFFFFu, s[r], o);
        if (s[r] > tlo) {   // uniform across warp (s[r] identical post-reduce)
            accA.x += a[r].x; accA.y += a[r].y; accA.z += a[r].z; accA.w += a[r].w;
            accC.x += c[r].x; accC.y += c[r].y; accC.z += c[r].z; accC.w += c[r].w;
        }
    }
    if (lane < 4) dots[row0 + lane] = s[lane];

    sA[warp][lane] = accA;   // lane l covers cols 4l..4l+3
    sC[warp][lane] = accC;   // lane l covers cols 128+4l..128+4l+3
    __syncthreads();

    if (tid < 256) {
        int col = tid;
        float v = 0.f;
        if (col < 128) {
            int l = col >> 2, m = col & 3;
#pragma unroll
            for (int w = 0; w < 16; w++)
                v += reinterpret_cast<const float*>(&sA[w][l])[m];
        } else {
            int cc = col - 128;
            int l = cc >> 2, m = cc & 3;
#pragma unroll
            for (int w = 0; w < 16; w++)
                v += reinterpret_cast<const float*>(&sC[w][l])[m];
        }
        int graph = blockIdx.x / blocksPerGraph;
        atomicAdd(&out[(size_t)graph * D + col], v);
    }
}

// ---------------- kernel 2: radix select -> sub/add correction lists ----------
// One block (1024 thr) per graph. Finds exact top-K threshold, then emits:
//   sub list: accumulated (key > keyLo) but NOT selected  (~4% of rows)
//   add list: selected but NOT accumulated                (~0; exactness net)
__global__ void __launch_bounds__(1024)
select_kernel(const float* __restrict__ dots, int N, int K) {
    __shared__ unsigned keys[4096];
    __shared__ unsigned hist[256];
    __shared__ unsigned warpTot[8];
    __shared__ unsigned s_chosen;
    __shared__ unsigned s_need;
    __shared__ int cntEQ, cntSub, cntAdd;

    int b = blockIdx.x, tid = threadIdx.x;
    int lane = tid & 31, warp = tid >> 5;
    const float* d = dots + (size_t)b * N;
    const unsigned FULL = 0xFFFFFFFFu;

    for (int i = tid; i < N; i += blockDim.x) {
        unsigned u = __float_as_uint(d[i]);
        u ^= (u >> 31) ? 0xFFFFFFFFu : 0x80000000u;  // order-preserving
        keys[i] = u;
    }
    if (tid == 0) s_need = (unsigned)K;
    __syncthreads();

    unsigned prefix = 0, mask = 0;
#pragma unroll
    for (int pass = 0; pass < 4; pass++) {
        int shift = 24 - 8 * pass;
        unsigned need = s_need;
        if (tid < 256) hist[tid] = 0;
        __syncthreads();
        for (int i = tid; i < N; i += blockDim.x) {
            unsigned kk = keys[i];
            bool pred = ((kk & mask) == prefix);
            unsigned bin = (kk >> shift) & 0xFFu;
            unsigned act = __ballot_sync(FULL, pred);
            if (pred) {
                unsigned mm = __match_any_sync(act, bin);
                int leader = __ffs(mm) - 1;
                if (lane == leader) atomicAdd(&hist[bin], (unsigned)__popc(mm));
            }
        }
        __syncthreads();
        if (warp < 8) {
            unsigned sum = hist[warp * 32 + lane];
#pragma unroll
            for (int o = 1; o < 32; o <<= 1) {
                unsigned t = __shfl_down_sync(FULL, sum, o);
                if (lane + o < 32) sum += t;
            }
            if (lane == 0) warpTot[warp] = sum;
            __syncwarp();
            hist[warp * 32 + lane] = sum;
        }
        __syncthreads();
        if (tid < 256) {
            unsigned add = 0;
            int myw = tid >> 5;
#pragma unroll
            for (int w = 0; w < 8; w++)
                if (w > myw) add += warpTot[w];
            unsigned st = hist[tid] + add;
            unsigned sn;
            if (tid == 255) sn = 0;
            else if ((tid & 31) == 31) sn = add;
            else sn = hist[tid + 1] + add;
            if (st >= need && sn < need) {
                s_chosen = (unsigned)tid;
                s_need = need - sn;
            }
        }
        __syncthreads();
        prefix |= s_chosen << shift;
        mask   |= 0xFFu << shift;
        __syncthreads();
    }

    unsigned thr = prefix;
    int budget = (int)s_need;          // EQ(thr) rows to take
    if (tid == 0) { cntEQ = 0; cntSub = 0; cntAdd = 0; }
    __syncthreads();

    // keyLo from the speculative threshold used in dot_acc (exact same value)
    float tloV = g_tlo;
    unsigned keyLo;
    {
        unsigned u = __float_as_uint(tloV);
        keyLo = u ^ ((u >> 31) ? 0xFFFFFFFFu : 0x80000000u);
    }

    int* subL = g_sub + (size_t)b * N;
    int* addL = g_add + (size_t)b * N;
    unsigned lmLT = (1u << lane) - 1u;

    for (int i = tid; i < N; i += blockDim.x) {
        unsigned kk = keys[i];
        bool isEQ = (kk == thr);
        bool selEQ = false;
        unsigned bEQ = __ballot_sync(FULL, isEQ);
        if (bEQ) {
            int base = 0;
            int leader = __ffs(bEQ) - 1;
            if (lane == leader) base = atomicAdd(&cntEQ, __popc(bEQ));
            base = __shfl_sync(FULL, base, leader);
            if (isEQ) selEQ = (base + __popc(bEQ & lmLT)) < budget;
        }
        bool sel = (kk > thr) || selEQ;
        bool acc = (kk > keyLo);
        bool doSub = acc && !sel;
        bool doAdd = sel && !acc;

        unsigned bS = __ballot_sync(FULL, doSub);
        if (bS) {
            int base = 0;
            int leader = __ffs(bS) - 1;
            if (lane == leader) base = atomicAdd(&cntSub, __popc(bS));
            base = __shfl_sync(FULL, base, leader);
            if (doSub) subL[base + __popc(bS & lmLT)] = b * N + i;
        }
        unsigned bA = __ballot_sync(FULL, doAdd);
        if (bA) {
            int base = 0;
            int leader = __ffs(bA) - 1;
            if (lane == leader) base = atomicAdd(&cntAdd, __popc(bA));
            base = __shfl_sync(FULL, base, leader);
            if (doAdd) addL[base + __popc(bA & lmLT)] = b * N + i;
        }
    }
    __syncthreads();
    if (tid == 0) { g_subCnt[b] = cntSub; g_addCnt[b] = cntAdd; }
}

// ---------------- kernel 3: correction gather (sub / add, tiny) ----------------
#define CSLICES 8
__device__ __forceinline__ float4 wave_sum(const int* list, int cnt, int st,
                                           const float4* lg4, int nD4, int l64) {
    float4 acc = make_float4(0.f, 0.f, 0.f, 0.f);
    for (int w0 = st; w0 < cnt; w0 += 32 * 6) {
        int rows[6];
#pragma unroll
        for (int j = 0; j < 6; j++) {
            int r = w0 + 32 * j;
            if (r < cnt) rows[j] = __ldg(&list[r]);
        }
        float4 v[6];
#pragma unroll
        for (int j = 0; j < 6; j++) {
            int r = w0 + 32 * j;
            if (r < cnt) v[j] = lg4[(size_t)rows[j] * nD4 + l64];
        }
#pragma unroll
        for (int j = 0; j < 6; j++) {
            int r = w0 + 32 * j;
            if (r < cnt) {
                acc.x += v[j].x; acc.y += v[j].y;
                acc.z += v[j].z; acc.w += v[j].w;
            }
        }
    }
    return acc;
}

__global__ void __launch_bounds__(256)
correct_kernel(const float* __restrict__ logits,
               float* __restrict__ out, int N, int D) {
    __shared__ float4 part[4][64];

    int b = blockIdx.x / CSLICES;
    int s = blockIdx.x % CSLICES;
    int tid = threadIdx.x;
    int grp = tid >> 6, l64 = tid & 63;

    int cS = g_subCnt[b];
    int cA = g_addCnt[b];
    if (cS == 0 && cA == 0) return;

    const float4* lg4 = reinterpret_cast<const float4*>(logits);
    int nD4 = D >> 2;
    int st = s * 4 + grp;   // 32 streams (8 slices x 4 groups), stride 32

    float4 aS = wave_sum(g_sub + (size_t)b * N, cS, st, lg4, nD4, l64);
    float4 aA = wave_sum(g_add + (size_t)b * N, cA, st, lg4, nD4, l64);
    float4 net = make_float4(aA.x - aS.x, aA.y - aS.y, aA.z - aS.z, aA.w - aS.w);

    part[grp][l64] = net;
    __syncthreads();

    int col = tid >> 2, comp = tid & 3;
    const float* q0 = reinterpret_cast<const float*>(&part[0][col]);
    const float* q1 = reinterpret_cast<const float*>(&part[1][col]);
    const float* q2 = reinterpret_cast<const float*>(&part[2][col]);
    const float* q3 = reinterpret_cast<const float*>(&part[3][col]);
    float vsum = (q0[comp] + q1[comp]) + (q2[comp] + q3[comp]);
    atomicAdd(&out[(size_t)b * D + tid], vsum);
}

// ---------------- launcher ----------------
extern "C" void kernel_launch(void* const* d_in, const int* in_sizes, int n_in,
                              void* d_out, int out_size) {
    const float* logits = (const float*)d_in[0];
    const float* proj = (const float*)d_in[2];
    float* out = (float*)d_out;

    int D = in_sizes[2];                 // 256
    int T = in_sizes[1];                 // 262144
    int B = out_size / D;                // 64
    int N = T / B;                       // 4096
    int K = (int)ceil(0.2 * (double)N);  // 820

    float* dots;
    cudaGetSymbolAddress((void**)&dots, g_dot);

    int blocksPerGraph = N / 64;         // 64

    // 0) zero output (provisional sums accumulate into it)
    cudaMemsetAsync(out, 0, (size_t)out_size * sizeof(float), 0);

    // 1) dots + speculative accumulation of rows with dot > 0.72*||p||
    dot_acc_kernel<<<T / 64, 512>>>(logits, proj, dots, out, blocksPerGraph, D);

    // 2) exact top-K threshold -> sub/add correction lists
    select_kernel<<<B, 1024>>>(dots, N, K);

    // 3) tiny correction gather (subtract over-included, add missed rows)
    correct_kernel<<<B * CSLICES, 256>>>(logits, out, N, D);
}

// round 16
// speedup vs baseline: 1.0195x; 1.0195x over previous
#include <cuda_runtime.h>
#include <math.h>

// ---------------- scratch (no allocs allowed) ----------------
#define MAX_T (64 * 4096)
#define MAX_B 64
__device__ float g_dot[MAX_T];       // per-node dot(logits, proj)
__device__ int   g_sub[MAX_T];       // per-graph subtract lists (stride N)
__device__ int   g_add[MAX_T];       // per-graph add lists (stride N)
__device__ int   g_subCnt[MAX_B];
__device__ int   g_addCnt[MAX_B];
__device__ float g_tlo;              // speculative accumulation threshold

// ---------------- kernel 1: dot + speculative accumulate ----------------
// One warp per 4 rows (512 thr = 64 rows/block; block never straddles a graph).
// Rows with dot > t_lo (~24%) are folded into a[0]/c[0] (registers already
// live -> zero extra register cost), block-reduced in smem, atomically added
// to out. t_lo = 0.72*||proj||, ~5.4 sigma below the expected top-20%
// threshold of N(0,||p||^2) dots. __launch_bounds__(512,3) pins regs <= 42
// so 3 blocks/SM fit (the R15 regression was 45 regs -> 2 blocks -> occ 47%).
__global__ void __launch_bounds__(512, 3)
dot_acc_kernel(const float* __restrict__ logits,
               const float* __restrict__ proj,
               float* __restrict__ dots,
               float* __restrict__ out,
               int blocksPerGraph, int D) {
    __shared__ float4 pS[64];
    __shared__ float4 sA[16][32];   // per-warp accumulators, cols 0..127
    __shared__ float4 sC[16][32];   // cols 128..255

    int tid = threadIdx.x;
    if (tid < 64) pS[tid] = reinterpret_cast<const float4*>(proj)[tid];
    __syncthreads();

    int warp = tid >> 5, lane = tid & 31;
    int row0 = (blockIdx.x * 16 + warp) * 4;

    float4 pa = pS[lane];
    float4 pc = pS[lane + 32];

    // ||proj||^2 via warp reduce (identical in every warp/block)
    float nrm = pa.x * pa.x + pa.y * pa.y + pa.z * pa.z + pa.w * pa.w
              + pc.x * pc.x + pc.y * pc.y + pc.z * pc.z + pc.w * pc.w;
#pragma unroll
    for (int o = 16; o; o >>= 1) nrm += __shfl_xor_sync(0xFFFFFFFFu, nrm, o);
    float tlo = 0.72f * sqrtf(nrm);
    if (blockIdx.x == 0 && tid == 0) g_tlo = tlo;

    const float4* rp = reinterpret_cast<const float4*>(logits) + (size_t)row0 * 64;

    float4 a[4], c[4];
#pragma unroll
    for (int r = 0; r < 4; r++) {
        a[r] = rp[(size_t)r * 64 + lane];
        c[r] = rp[(size_t)r * 64 + lane + 32];
    }

    float s[4];
#pragma unroll
    for (int r = 0; r < 4; r++) {
        s[r] = a[r].x * pa.x + a[r].y * pa.y + a[r].z * pa.z + a[r].w * pa.w
             + c[r].x * pc.x + c[r].y * pc.y + c[r].z * pc.z + c[r].w * pc.w;
#pragma unroll
        for (int o = 16; o; o >>= 1) s[r] += __shfl_xor_sync(0xFFFFFFFFu, s[r], o);
    }
    if (lane < 4) dots[row0 + lane] = s[lane];

    // fold selected rows into a[0]/c[0] (registers dead after s[] computed;
    // conditions are warp-uniform since s[r] is identical across lanes)
    if (s[0] <= tlo) {
        a[0] = make_float4(0.f, 0.f, 0.f, 0.f);
        c[0] = make_float4(0.f, 0.f, 0.f, 0.f);
    }
#pragma unroll
    for (int r = 1; r < 4; r++) {
        if (s[r] > tlo) {
            a[0].x += a[r].x; a[0].y += a[r].y; a[0].z += a[r].z; a[0].w += a[r].w;
            c[0].x += c[r].x; c[0].y += c[r].y; c[0].z += c[r].z; c[0].w += c[r].w;
        }
    }

    sA[warp][lane] = a[0];   // lane l covers cols 4l..4l+3
    sC[warp][lane] = c[0];   // lane l covers cols 128+4l..128+4l+3
    __syncthreads();

    if (tid < 256) {
        int col = tid;
        float v = 0.f;
        if (col < 128) {
            int l = col >> 2, m = col & 3;
#pragma unroll
            for (int w = 0; w < 16; w++)
                v += reinterpret_cast<const float*>(&sA[w][l])[m];
        } else {
            int cc = col - 128;
            int l = cc >> 2, m = cc & 3;
#pragma unroll
            for (int w = 0; w < 16; w++)
                v += reinterpret_cast<const float*>(&sC[w][l])[m];
        }
        int graph = blockIdx.x / blocksPerGraph;
        atomicAdd(&out[(size_t)graph * D + col], v);
    }
}

// ---------------- kernel 2: radix select -> sub/add correction lists ----------
// One block (1024 thr) per graph. Finds exact top-K threshold, then emits:
//   sub list: accumulated (key > keyLo) but NOT selected  (~4% of rows)
//   add list: selected but NOT accumulated                (~0; exactness net)
__global__ void __launch_bounds__(1024)
select_kernel(const float* __restrict__ dots, int N, int K) {
    __shared__ unsigned keys[4096];
    __shared__ unsigned hist[256];
    __shared__ unsigned warpTot[8];
    __shared__ unsigned s_chosen;
    __shared__ unsigned s_need;
    __shared__ int cntEQ, cntSub, cntAdd;

    int b = blockIdx.x, tid = threadIdx.x;
    int lane = tid & 31, warp = tid >> 5;
    const float* d = dots + (size_t)b * N;
    const unsigned FULL = 0xFFFFFFFFu;

    for (int i = tid; i < N; i += blockDim.x) {
        unsigned u = __float_as_uint(d[i]);
        u ^= (u >> 31) ? 0xFFFFFFFFu : 0x80000000u;  // order-preserving
        keys[i] = u;
    }
    if (tid == 0) s_need = (unsigned)K;
    __syncthreads();

    unsigned prefix = 0, mask = 0;
#pragma unroll
    for (int pass = 0; pass < 4; pass++) {
        int shift = 24 - 8 * pass;
        unsigned need = s_need;
        if (tid < 256) hist[tid] = 0;
        __syncthreads();
        for (int i = tid; i < N; i += blockDim.x) {
            unsigned kk = keys[i];
            bool pred = ((kk & mask) == prefix);
            unsigned bin = (kk >> shift) & 0xFFu;
            unsigned act = __ballot_sync(FULL, pred);
            if (pred) {
                unsigned mm = __match_any_sync(act, bin);
                int leader = __ffs(mm) - 1;
                if (lane == leader) atomicAdd(&hist[bin], (unsigned)__popc(mm));
            }
        }
        __syncthreads();
        if (warp < 8) {
            unsigned sum = hist[warp * 32 + lane];
#pragma unroll
            for (int o = 1; o < 32; o <<= 1) {
                unsigned t = __shfl_down_sync(FULL, sum, o);
                if (lane + o < 32) sum += t;
            }
            if (lane == 0) warpTot[warp] = sum;
            __syncwarp();
            hist[warp * 32 + lane] = sum;
        }
        __syncthreads();
        if (tid < 256) {
            unsigned add = 0;
            int myw = tid >> 5;
#pragma unroll
            for (int w = 0; w < 8; w++)
                if (w > myw) add += warpTot[w];
            unsigned st = hist[tid] + add;
            unsigned sn;
            if (tid == 255) sn = 0;
            else if ((tid & 31) == 31) sn = add;
            else sn = hist[tid + 1] + add;
            if (st >= need && sn < need) {
                s_chosen = (unsigned)tid;
                s_need = need - sn;
            }
        }
        __syncthreads();
        prefix |= s_chosen << shift;
        mask   |= 0xFFu << shift;
        __syncthreads();
    }

    unsigned thr = prefix;
    int budget = (int)s_need;          // EQ(thr) rows to take
    if (tid == 0) { cntEQ = 0; cntSub = 0; cntAdd = 0; }
    __syncthreads();

    // keyLo from the speculative threshold used in dot_acc (bitwise same value)
    float tloV = g_tlo;
    unsigned keyLo;
    {
        unsigned u = __float_as_uint(tloV);
        keyLo = u ^ ((u >> 31) ? 0xFFFFFFFFu : 0x80000000u);
    }

    int* subL = g_sub + (size_t)b * N;
    int* addL = g_add + (size_t)b * N;
    unsigned lmLT = (1u << lane) - 1u;

    for (int i = tid; i < N; i += blockDim.x) {
        unsigned kk = keys[i];
        bool isEQ = (kk == thr);
        bool selEQ = false;
        unsigned bEQ = __ballot_sync(FULL, isEQ);
        if (bEQ) {
            int base = 0;
            int leader = __ffs(bEQ) - 1;
            if (lane == leader) base = atomicAdd(&cntEQ, __popc(bEQ));
            base = __shfl_sync(FULL, base, leader);
            if (isEQ) selEQ = (base + __popc(bEQ & lmLT)) < budget;
        }
        bool sel = (kk > thr) || selEQ;
        bool acc = (kk > keyLo);
        bool doSub = acc && !sel;
        bool doAdd = sel && !acc;

        unsigned bS = __ballot_sync(FULL, doSub);
        if (bS) {
            int base = 0;
            int leader = __ffs(bS) - 1;
            if (lane == leader) base = atomicAdd(&cntSub, __popc(bS));
            base = __shfl_sync(FULL, base, leader);
            if (doSub) subL[base + __popc(bS & lmLT)] = b * N + i;
        }
        unsigned bA = __ballot_sync(FULL, doAdd);
        if (bA) {
            int base = 0;
            int leader = __ffs(bA) - 1;
            if (lane == leader) base = atomicAdd(&cntAdd, __popc(bA));
            base = __shfl_sync(FULL, base, leader);
            if (doAdd) addL[base + __popc(bA & lmLT)] = b * N + i;
        }
    }
    __syncthreads();
    if (tid == 0) { g_subCnt[b] = cntSub; g_addCnt[b] = cntAdd; }
}

// ---------------- kernel 3: correction gather (sub / add, tiny) ----------------
#define CSLICES 8
__device__ __forceinline__ float4 wave_sum(const int* list, int cnt, int st,
                                           const float4* lg4, int nD4, int l64) {
    float4 acc = make_float4(0.f, 0.f, 0.f, 0.f);
    for (int w0 = st; w0 < cnt; w0 += 32 * 6) {
        int rows[6];
#pragma unroll
        for (int j = 0; j < 6; j++) {
            int r = w0 + 32 * j;
            if (r < cnt) rows[j] = __ldg(&list[r]);
        }
        float4 v[6];
#pragma unroll
        for (int j = 0; j < 6; j++) {
            int r = w0 + 32 * j;
            if (r < cnt) v[j] = lg4[(size_t)rows[j] * nD4 + l64];
        }
#pragma unroll
        for (int j = 0; j < 6; j++) {
            int r = w0 + 32 * j;
            if (r < cnt) {
                acc.x += v[j].x; acc.y += v[j].y;
                acc.z += v[j].z; acc.w += v[j].w;
            }
        }
    }
    return acc;
}

__global__ void __launch_bounds__(256)
correct_kernel(const float* __restrict__ logits,
               float* __restrict__ out, int N, int D) {
    __shared__ float4 part[4][64];

    int b = blockIdx.x / CSLICES;
    int s = blockIdx.x % CSLICES;
    int tid = threadIdx.x;
    int grp = tid >> 6, l64 = tid & 63;

    int cS = g_subCnt[b];
    int cA = g_addCnt[b];
    if (cS == 0 && cA == 0) return;

    const float4* lg4 = reinterpret_cast<const float4*>(logits);
    int nD4 = D >> 2;
    int st = s * 4 + grp;   // 32 streams (8 slices x 4 groups), stride 32

    float4 aS = wave_sum(g_sub + (size_t)b * N, cS, st, lg4, nD4, l64);
    float4 aA = wave_sum(g_add + (size_t)b * N, cA, st, lg4, nD4, l64);
    float4 net = make_float4(aA.x - aS.x, aA.y - aS.y, aA.z - aS.z, aA.w - aS.w);

    part[grp][l64] = net;
    __syncthreads();

    int col = tid >> 2, comp = tid & 3;
    const float* q0 = reinterpret_cast<const float*>(&part[0][col]);
    const float* q1 = reinterpret_cast<const float*>(&part[1][col]);
    const float* q2 = reinterpret_cast<const float*>(&part[2][col]);
    const float* q3 = reinterpret_cast<const float*>(&part[3][col]);
    float vsum = (q0[comp] + q1[comp]) + (q2[comp] + q3[comp]);
    atomicAdd(&out[(size_t)b * D + tid], vsum);
}

// ---------------- launcher ----------------
extern "C" void kernel_launch(void* const* d_in, const int* in_sizes, int n_in,
                              void* d_out, int out_size) {
    const float* logits = (const float*)d_in[0];
    const float* proj = (const float*)d_in[2];
    float* out = (float*)d_out;

    int D = in_sizes[2];                 // 256
    int T = in_sizes[1];                 // 262144
    int B = out_size / D;                // 64
    int N = T / B;                       // 4096
    int K = (int)ceil(0.2 * (double)N);  // 820

    float* dots;
    cudaGetSymbolAddress((void**)&dots, g_dot);

    int blocksPerGraph = N / 64;         // 64

    // 0) zero output (provisional sums accumulate into it)
    cudaMemsetAsync(out, 0, (size_t)out_size * sizeof(float), 0);

    // 1) dots + speculative accumulation of rows with dot > 0.72*||p||
    dot_acc_kernel<<<T / 64, 512>>>(logits, proj, dots, out, blocksPerGraph, D);

    // 2) exact top-K threshold -> sub/add correction lists
    select_kernel<<<B, 1024>>>(dots, N, K);

    // 3) tiny correction gather (subtract over-included, add missed rows)
    correct_kernel<<<B * CSLICES, 256>>>(logits, out, N, D);
}